// round 1
// baseline (speedup 1.0000x reference)
#include <cuda_runtime.h>
#include <math.h>

#define BSZ 8
#define SEQ 1024
#define DIM 768
#define NH  12
#define DKH 64
#define NL  3
#define MTOT (BSZ*SEQ)   // 8192

// ---------------- scratch (no allocations allowed) ----------------
__device__ float g_q  [MTOT*DIM];
__device__ float g_k  [MTOT*DIM];
__device__ float g_v  [MTOT*DIM];
__device__ float g_ctx[MTOT*DIM];
__device__ float g_pp [MTOT*DIM];

// ======================================================================
// linear: out[M,N] = X[M,768] @ W[N,768]^T + bias[N]  (+ add[M,N] optional)
// Tile: 128(M) x 64(N) x 32(K). 256 threads, 8x4 micro-tile per thread.
// ======================================================================
__global__ __launch_bounds__(256) void linear_kernel(
    const float* __restrict__ X, const float* __restrict__ W,
    const float* __restrict__ bias, const float* __restrict__ add,
    float* __restrict__ out)
{
    __shared__ float Xs[128][33];
    __shared__ float Ws[64][33];

    const int tid = threadIdx.x;
    const int tx  = tid & 15;       // 0..15 -> N
    const int ty  = tid >> 4;       // 0..15 -> M
    const int m0  = blockIdx.y * 128;
    const int n0  = blockIdx.x * 64;

    float acc[8][4];
    #pragma unroll
    for (int r = 0; r < 8; r++)
        #pragma unroll
        for (int c = 0; c < 4; c++) acc[r][c] = 0.f;

    for (int k0 = 0; k0 < DIM; k0 += 32) {
        // load X tile 128x32 (gmem coalesced along k; smem conflict-free)
        #pragma unroll
        for (int i = 0; i < 16; i++) {
            int idx = tid + i * 256;
            int m = idx >> 5, kk = idx & 31;
            Xs[m][kk] = X[(size_t)(m0 + m) * DIM + k0 + kk];
        }
        // load W tile 64x32
        #pragma unroll
        for (int i = 0; i < 8; i++) {
            int idx = tid + i * 256;
            int n = idx >> 5, kk = idx & 31;
            Ws[n][kk] = W[(size_t)(n0 + n) * DIM + k0 + kk];
        }
        __syncthreads();

        #pragma unroll
        for (int kk = 0; kk < 32; kk++) {
            float xr[8], wc[4];
            #pragma unroll
            for (int r = 0; r < 8; r++) xr[r] = Xs[ty * 8 + r][kk];
            #pragma unroll
            for (int c = 0; c < 4; c++) wc[c] = Ws[tx * 4 + c][kk];
            #pragma unroll
            for (int r = 0; r < 8; r++)
                #pragma unroll
                for (int c = 0; c < 4; c++)
                    acc[r][c] = fmaf(xr[r], wc[c], acc[r][c]);
        }
        __syncthreads();
    }

    #pragma unroll
    for (int r = 0; r < 8; r++) {
        int m = m0 + ty * 8 + r;
        #pragma unroll
        for (int c = 0; c < 4; c++) {
            int n = n0 + tx * 4 + c;
            float val = acc[r][c] + bias[n];
            if (add) val += add[(size_t)m * DIM + n];
            out[(size_t)m * DIM + n] = val;
        }
    }
}

// ======================================================================
// Fused attention (flash-style, post-softmax mask folded into numerator):
//   ctx[q,:] = ( sum_k exp(s_qk - m_q) * mask_qk * v_k ) / ( sum_k exp(s_qk - m_q) )
// Per block: one (b,h) and 64 query rows. Loop over 16 K-tiles of 64.
// 256 threads, 4x4 micro-tiles. Dynamic smem: 4 x 64x65 fp32 = 66560 B.
// ======================================================================
__global__ __launch_bounds__(256) void attn_kernel(
    const float* __restrict__ q, const float* __restrict__ k,
    const float* __restrict__ v, const float* __restrict__ dist,
    float* __restrict__ ctx)
{
    extern __shared__ float sm[];
    float* Qs = sm;                 // [64][65]  (row = q row, col = d)
    float* Ks = Qs + 64 * 65;       // [64][65]  (row = k row, col = d)
    float* Vs = Ks + 64 * 65;       // [64][65]  (row = k row, col = d)
    float* Ps = Vs + 64 * 65;       // [64][65]  (row = q row, col = k col)

    const int tid = threadIdx.x;
    const int tx  = tid & 15;       // k cols / dk cols
    const int ty  = tid >> 4;       // q rows
    const int b   = blockIdx.z;
    const int h   = blockIdx.y;
    const int q0  = blockIdx.x * 64;

    const float* qb = q + (size_t)b * SEQ * DIM + h * DKH;
    const float* kb = k + (size_t)b * SEQ * DIM + h * DKH;
    const float* vb = v + (size_t)b * SEQ * DIM + h * DKH;
    const float* db = dist + (size_t)b * SEQ * SEQ;

    // load Q tile once
    #pragma unroll
    for (int i = 0; i < 16; i++) {
        int idx = tid + i * 256;
        int d = idx & 63, row = idx >> 6;
        Qs[row * 65 + d] = qb[(size_t)(q0 + row) * DIM + d];
    }

    float m_run[4], z_run[4], O[4][4];
    #pragma unroll
    for (int r = 0; r < 4; r++) {
        m_run[r] = -1e30f; z_run[r] = 0.f;
        #pragma unroll
        for (int c = 0; c < 4; c++) O[r][c] = 0.f;
    }
    __syncthreads();

    for (int kt = 0; kt < SEQ / 64; kt++) {
        const int k0 = kt * 64;
        // load K,V tiles
        #pragma unroll
        for (int i = 0; i < 16; i++) {
            int idx = tid + i * 256;
            int d = idx & 63, row = idx >> 6;
            Ks[row * 65 + d] = kb[(size_t)(k0 + row) * DIM + d];
            Vs[row * 65 + d] = vb[(size_t)(k0 + row) * DIM + d];
        }
        __syncthreads();

        // S = Q @ K^T / 8
        float s[4][4];
        #pragma unroll
        for (int r = 0; r < 4; r++)
            #pragma unroll
            for (int c = 0; c < 4; c++) s[r][c] = 0.f;
        #pragma unroll 8
        for (int d = 0; d < 64; d++) {
            float qd[4], kd[4];
            #pragma unroll
            for (int r = 0; r < 4; r++) qd[r] = Qs[(ty * 4 + r) * 65 + d];
            #pragma unroll
            for (int c = 0; c < 4; c++) kd[c] = Ks[(tx * 4 + c) * 65 + d];
            #pragma unroll
            for (int r = 0; r < 4; r++)
                #pragma unroll
                for (int c = 0; c < 4; c++)
                    s[r][c] = fmaf(qd[r], kd[c], s[r][c]);
        }

        // online softmax per q-row (reduce across the 16 tx threads)
        #pragma unroll
        for (int r = 0; r < 4; r++) {
            float mloc = -1e30f;
            #pragma unroll
            for (int c = 0; c < 4; c++) {
                s[r][c] *= 0.125f;
                mloc = fmaxf(mloc, s[r][c]);
            }
            #pragma unroll
            for (int off = 8; off > 0; off >>= 1)
                mloc = fmaxf(mloc, __shfl_xor_sync(0xffffffffu, mloc, off));

            float mnew = fmaxf(m_run[r], mloc);
            float factor = __expf(m_run[r] - mnew);
            z_run[r] *= factor;
            #pragma unroll
            for (int c = 0; c < 4; c++) O[r][c] *= factor;

            const int qi = q0 + ty * 4 + r;
            float4 dv = *reinterpret_cast<const float4*>(
                db + (size_t)qi * SEQ + k0 + tx * 4);
            float mk[4] = {dv.x, dv.y, dv.z, dv.w};

            float rowsum = 0.f;
            #pragma unroll
            for (int c = 0; c < 4; c++) {
                float e = __expf(s[r][c] - mnew);
                rowsum += e;
                const int ki = k0 + tx * 4 + c;
                float mask = mk[c] + (qi == ki ? 1.0f : 0.0f);
                Ps[(ty * 4 + r) * 65 + tx * 4 + c] = e * mask;
            }
            #pragma unroll
            for (int off = 8; off > 0; off >>= 1)
                rowsum += __shfl_xor_sync(0xffffffffu, rowsum, off);

            z_run[r] += rowsum;
            m_run[r] = mnew;
        }
        __syncthreads();

        // O += P~ @ V
        #pragma unroll 8
        for (int j = 0; j < 64; j++) {
            float pv[4], vv[4];
            #pragma unroll
            for (int r = 0; r < 4; r++) pv[r] = Ps[(ty * 4 + r) * 65 + j];
            #pragma unroll
            for (int c = 0; c < 4; c++) vv[c] = Vs[j * 65 + tx * 4 + c];
            #pragma unroll
            for (int r = 0; r < 4; r++)
                #pragma unroll
                for (int c = 0; c < 4; c++)
                    O[r][c] = fmaf(pv[r], vv[c], O[r][c]);
        }
        __syncthreads();
    }

    // epilogue: normalize + store ctx in [B,S,D] layout
    #pragma unroll
    for (int r = 0; r < 4; r++) {
        float inv = 1.0f / z_run[r];
        const size_t row = (size_t)b * SEQ + q0 + ty * 4 + r;
        #pragma unroll
        for (int c = 0; c < 4; c++)
            ctx[row * DIM + h * DKH + tx * 4 + c] = O[r][c] * inv;
    }
}

// ======================================================================
// host orchestration
// ======================================================================
extern "C" void kernel_launch(void* const* d_in, const int* in_sizes, int n_in,
                              void* d_out, int out_size)
{
    const float* Q    = (const float*)d_in[0];
    const float* Kin  = (const float*)d_in[1];
    const float* Vin  = (const float*)d_in[2];
    const float* dist = (const float*)d_in[3];
    const float* Wq   = (const float*)d_in[4];
    const float* bq   = (const float*)d_in[5];
    const float* Wk   = (const float*)d_in[6];
    const float* bk   = (const float*)d_in[7];
    const float* Wv   = (const float*)d_in[8];
    const float* bv   = (const float*)d_in[9];
    const float* Wo   = (const float*)d_in[10];
    const float* bo   = (const float*)d_in[11];
    float* out = (float*)d_out;

    float *q_buf, *k_buf, *v_buf, *ctx_buf, *pp_buf;
    cudaGetSymbolAddress((void**)&q_buf,   g_q);
    cudaGetSymbolAddress((void**)&k_buf,   g_k);
    cudaGetSymbolAddress((void**)&v_buf,   g_v);
    cudaGetSymbolAddress((void**)&ctx_buf, g_ctx);
    cudaGetSymbolAddress((void**)&pp_buf,  g_pp);

    const int ATTN_SMEM = 4 * 64 * 65 * (int)sizeof(float); // 66560 B
    cudaFuncSetAttribute(attn_kernel,
                         cudaFuncAttributeMaxDynamicSharedMemorySize, ATTN_SMEM);

    dim3 lgrid(DIM / 64, MTOT / 128);   // (12, 64)
    dim3 agrid(SEQ / 64, NH, BSZ);      // (16, 12, 8)

    const float* curK = Kin;
    const float* curV = Vin;
    for (int i = 0; i < NL; i++) {
        const size_t wo = (size_t)i * DIM * DIM;
        const size_t bofs = (size_t)i * DIM;
        linear_kernel<<<lgrid, 256>>>(Q,    Wq + wo, bq + bofs, nullptr, q_buf);
        linear_kernel<<<lgrid, 256>>>(curK, Wk + wo, bk + bofs, nullptr, k_buf);
        linear_kernel<<<lgrid, 256>>>(curV, Wv + wo, bv + bofs, nullptr, v_buf);
        attn_kernel<<<agrid, 256, ATTN_SMEM>>>(q_buf, k_buf, v_buf, dist, ctx_buf);
        float* dst = (i == NL - 1) ? out : pp_buf;
        linear_kernel<<<lgrid, 256>>>(ctx_buf, Wo + wo, bo + bofs,
                                      (i == NL - 1) ? Vin : nullptr, dst);
        curK = dst;
        curV = dst;
    }
}

// round 3
// speedup vs baseline: 3.2123x; 3.2123x over previous
#include <cuda_runtime.h>
#include <cstdint>
#include <math.h>

#define BSZ 8
#define SEQ 1024
#define DIM 768
#define NH  12
#define DKH 64
#define NL  3
#define MTOT (BSZ*SEQ)   // 8192

// ---------------- scratch (no allocations allowed) ----------------
__device__ float g_q  [MTOT*DIM];
__device__ float g_k  [MTOT*DIM];
__device__ float g_v  [MTOT*DIM];
__device__ float g_ctx[MTOT*DIM];
__device__ float g_pp [MTOT*DIM];

// ======================================================================
// helpers
// ======================================================================
__device__ __forceinline__ uint32_t smem_u32(const void* p) {
    uint32_t a;
    asm("{ .reg .u64 t; cvta.to.shared.u64 t, %1; cvt.u32.u64 %0, t; }"
        : "=r"(a) : "l"(p));
    return a;
}

// round-to-nearest fp32 -> tf32 (mandatory: truncation bias breaks 1e-3 gate)
__device__ __forceinline__ uint32_t f2tf(float x) {
    uint32_t r;
    asm("cvt.rna.tf32.f32 %0, %1;" : "=r"(r) : "f"(x));
    return r;
}

// D += A*B, m16n8k8 tf32
__device__ __forceinline__ void mma8(float* d, const uint32_t* a, const uint32_t* b) {
    asm volatile(
        "mma.sync.aligned.m16n8k8.row.col.f32.tf32.tf32.f32 "
        "{%0,%1,%2,%3}, {%4,%5,%6,%7}, {%8,%9}, {%0,%1,%2,%3};"
        : "+f"(d[0]), "+f"(d[1]), "+f"(d[2]), "+f"(d[3])
        : "r"(a[0]), "r"(a[1]), "r"(a[2]), "r"(a[3]), "r"(b[0]), "r"(b[1]));
}

#define CP_ASYNC16(s, g) \
    asm volatile("cp.async.cg.shared.global [%0], [%1], 16;" \
                 :: "r"(s), "l"(g) : "memory")
#define CP_COMMIT() asm volatile("cp.async.commit_group;" ::: "memory")
template<int N> __device__ __forceinline__ void cp_wait() {
    asm volatile("cp.async.wait_group %0;" :: "n"(N) : "memory");
}

// ======================================================================
// GEMM (tf32 mma.sync): out[M,N] = X[M,768] @ W[N,768]^T + bias (+add)
// CTA tile 128x128x32, 2-stage cp.async pipeline, 8 warps (4M x 2N),
// warp tile 32x64. Smem stride 36 -> fragment loads conflict-free.
// ======================================================================
#define GPAD  36
#define GSLOT (128*GPAD)                     // floats per A or B tile
#define GEMM_SMEM ((128 + 2*2*GSLOT) * 4)    // 74240 B

__global__ __launch_bounds__(256) void gemm_mma_kernel(
    const float* __restrict__ X, const float* __restrict__ W,
    const float* __restrict__ bias, const float* __restrict__ add,
    float* __restrict__ out)
{
    extern __shared__ float sm[];
    float* sBias  = sm;            // 128
    float* sTiles = sm + 128;      // [slot][A|B][GSLOT]
    const uint32_t tilesAddr = smem_u32(sTiles);

    const int tid  = threadIdx.x;
    const int lane = tid & 31, wid = tid >> 5;
    const int g = lane >> 2, t = lane & 3;
    const int wm = wid & 3, wn = wid >> 2;
    const int m0 = blockIdx.y * 128, n0 = blockIdx.x * 128;

    if (tid < 128) sBias[tid] = bias[n0 + tid];

    float acc[2][8][4];
    #pragma unroll
    for (int mt = 0; mt < 2; mt++)
        #pragma unroll
        for (int nt = 0; nt < 8; nt++)
            #pragma unroll
            for (int i = 0; i < 4; i++) acc[mt][nt][i] = 0.f;

    auto load_chunk = [&](int c) {
        const uint32_t base = tilesAddr + (uint32_t)(c & 1) * (2 * GSLOT * 4);
        const float* gA = X + (size_t)m0 * DIM + c * 32;
        const float* gB = W + (size_t)n0 * DIM + c * 32;
        #pragma unroll
        for (int i = 0; i < 4; i++) {
            int idx = tid + i * 256;          // 0..1023
            int row = idx >> 3, f4 = idx & 7;
            uint32_t d = base + (uint32_t)(row * GPAD + f4 * 4) * 4;
            const size_t go = (size_t)row * DIM + f4 * 4;
            CP_ASYNC16(d, gA + go);
            CP_ASYNC16(d + GSLOT * 4, gB + go);
        }
        CP_COMMIT();
    };

    load_chunk(0);
    for (int c = 0; c < 24; c++) {
        if (c + 1 < 24) { load_chunk(c + 1); cp_wait<1>(); }
        else            cp_wait<0>();
        __syncthreads();

        const float* A = sTiles + (size_t)(c & 1) * 2 * GSLOT;
        const float* B = A + GSLOT;

        #pragma unroll
        for (int ks = 0; ks < 4; ks++) {
            uint32_t af[2][4];
            #pragma unroll
            for (int mt = 0; mt < 2; mt++) {
                const float* ap = A + (wm * 32 + mt * 16 + g) * GPAD + ks * 8 + t;
                af[mt][0] = f2tf(ap[0]);
                af[mt][1] = f2tf(ap[8 * GPAD]);
                af[mt][2] = f2tf(ap[4]);
                af[mt][3] = f2tf(ap[8 * GPAD + 4]);
            }
            #pragma unroll
            for (int nt = 0; nt < 8; nt++) {
                const float* bp = B + (wn * 64 + nt * 8 + g) * GPAD + ks * 8 + t;
                uint32_t bf[2] = { f2tf(bp[0]), f2tf(bp[4]) };
                mma8(acc[0][nt], af[0], bf);
                mma8(acc[1][nt], af[1], bf);
            }
        }
        __syncthreads();
    }

    // epilogue: D frag (c0,c1)=(row, 2t..2t+1), (c2,c3)=(row+8, ...)
    #pragma unroll
    for (int mt = 0; mt < 2; mt++) {
        const int m = m0 + wm * 32 + mt * 16 + g;
        #pragma unroll
        for (int nt = 0; nt < 8; nt++) {
            const int nl = wn * 64 + nt * 8 + 2 * t;
            float2 v0, v1;
            v0.x = acc[mt][nt][0] + sBias[nl];
            v0.y = acc[mt][nt][1] + sBias[nl + 1];
            v1.x = acc[mt][nt][2] + sBias[nl];
            v1.y = acc[mt][nt][3] + sBias[nl + 1];
            const size_t o0 = (size_t)m * DIM + n0 + nl;
            const size_t o1 = (size_t)(m + 8) * DIM + n0 + nl;
            if (add) {
                float2 a0 = *reinterpret_cast<const float2*>(add + o0);
                float2 a1 = *reinterpret_cast<const float2*>(add + o1);
                v0.x += a0.x; v0.y += a0.y;
                v1.x += a1.x; v1.y += a1.y;
            }
            *reinterpret_cast<float2*>(out + o0) = v0;
            *reinterpret_cast<float2*>(out + o1) = v1;
        }
    }
}

// ======================================================================
// Fused flash attention with tf32 mma.sync.
// CTA = (b, h, 128 q rows). 8 warps; warp w owns q rows [w*16, w*16+16)
// and the FULL key range (softmax stats stay intra-warp).
// K/V double-buffered via cp.async; P round-trips through retired Q smem.
// Pads: K/Q/P stride 68, V stride 72 (both access patterns conflict-free).
// ======================================================================
#define KP 68
#define VP 72
#define KV_SLOT (64*KP + 64*VP)     // 8960 floats
#define QP_OFF  (2*KV_SLOT)         // 17920 floats
#define ATTN_SMEM ((2*KV_SLOT + 128*KP) * 4)   // 106496 B

__global__ __launch_bounds__(256, 1) void attn_mma_kernel(
    const float* __restrict__ q, const float* __restrict__ k,
    const float* __restrict__ v, const float* __restrict__ dist,
    float* __restrict__ ctx)
{
    extern __shared__ float sm[];
    float* sKV = sm;
    float* sQP = sm + QP_OFF;
    const uint32_t kvAddr = smem_u32(sm);

    const int tid  = threadIdx.x;
    const int lane = tid & 31, wid = tid >> 5;
    const int g = lane >> 2, t = lane & 3;
    const int b = blockIdx.z, h = blockIdx.y;
    const int q0 = blockIdx.x * 128;

    const float* qb = q + (size_t)b * SEQ * DIM + h * DKH;
    const float* kb = k + (size_t)b * SEQ * DIM + h * DKH;
    const float* vb = v + (size_t)b * SEQ * DIM + h * DKH;
    const float* db = dist + (size_t)b * SEQ * SEQ;

    // ---- load Q tile 128x64 into sQP ----
    #pragma unroll
    for (int i = 0; i < 8; i++) {
        int idx = tid + i * 256;        // 0..2047
        int row = idx >> 4, f4 = idx & 15;
        *reinterpret_cast<float4*>(sQP + row * KP + f4 * 4) =
            *reinterpret_cast<const float4*>(qb + (size_t)(q0 + row) * DIM + f4 * 4);
    }
    __syncthreads();

    // ---- extract Q fragments (tf32) once ----
    uint32_t qf[8][4];
    {
        const float* qp = sQP + (wid * 16 + g) * KP;
        #pragma unroll
        for (int ks = 0; ks < 8; ks++) {
            qf[ks][0] = f2tf(qp[ks * 8 + t]);
            qf[ks][1] = f2tf(qp[8 * KP + ks * 8 + t]);
            qf[ks][2] = f2tf(qp[ks * 8 + t + 4]);
            qf[ks][3] = f2tf(qp[8 * KP + ks * 8 + t + 4]);
        }
    }
    __syncthreads();   // sQP now reusable as P

    float Of[8][4];
    #pragma unroll
    for (int nt = 0; nt < 8; nt++)
        #pragma unroll
        for (int i = 0; i < 4; i++) Of[nt][i] = 0.f;
    float m_run0 = -1e30f, m_run1 = -1e30f, z_run0 = 0.f, z_run1 = 0.f;
    const int qi0 = q0 + wid * 16 + g;
    const int qi1 = qi0 + 8;

    auto load_kv = [&](int kt) {
        const uint32_t base = kvAddr + (uint32_t)(kt & 1) * (KV_SLOT * 4);
        const float* gk = kb + (size_t)kt * 64 * DIM;
        const float* gv = vb + (size_t)kt * 64 * DIM;
        #pragma unroll
        for (int i = 0; i < 4; i++) {
            int idx = tid + i * 256;     // 0..1023
            int row = idx >> 4, f4 = idx & 15;
            const size_t go = (size_t)row * DIM + f4 * 4;
            CP_ASYNC16(base + (uint32_t)(row * KP + f4 * 4) * 4, gk + go);
            CP_ASYNC16(base + (uint32_t)(64 * KP + row * VP + f4 * 4) * 4, gv + go);
        }
        CP_COMMIT();
    };

    load_kv(0);
    for (int kt = 0; kt < 16; kt++) {
        if (kt + 1 < 16) { load_kv(kt + 1); cp_wait<1>(); }
        else             cp_wait<0>();
        __syncthreads();

        const float* Ks = sKV + (size_t)(kt & 1) * KV_SLOT;
        const float* Vs = Ks + 64 * KP;
        const int kbase = kt * 64;

        // prefetch mask values (overlaps with S mma)
        float2 md0[8], md1[8];
        #pragma unroll
        for (int nt = 0; nt < 8; nt++) {
            md0[nt] = *reinterpret_cast<const float2*>(
                db + (size_t)qi0 * SEQ + kbase + nt * 8 + 2 * t);
            md1[nt] = *reinterpret_cast<const float2*>(
                db + (size_t)qi1 * SEQ + kbase + nt * 8 + 2 * t);
        }

        // ---- S = Q K^T ----
        float Sf[8][4];
        #pragma unroll
        for (int nt = 0; nt < 8; nt++)
            #pragma unroll
            for (int i = 0; i < 4; i++) Sf[nt][i] = 0.f;
        #pragma unroll
        for (int ks = 0; ks < 8; ks++) {
            #pragma unroll
            for (int nt = 0; nt < 8; nt++) {
                const float* kp = Ks + (nt * 8 + g) * KP + ks * 8 + t;
                uint32_t bf[2] = { f2tf(kp[0]), f2tf(kp[4]) };
                mma8(Sf[nt], qf[ks], bf);
            }
        }

        // ---- online softmax (rows qi0, qi1) ----
        float mloc0 = -1e30f, mloc1 = -1e30f;
        #pragma unroll
        for (int nt = 0; nt < 8; nt++) {
            #pragma unroll
            for (int i = 0; i < 4; i++) Sf[nt][i] *= 0.125f;
            mloc0 = fmaxf(mloc0, fmaxf(Sf[nt][0], Sf[nt][1]));
            mloc1 = fmaxf(mloc1, fmaxf(Sf[nt][2], Sf[nt][3]));
        }
        #pragma unroll
        for (int off = 1; off <= 2; off <<= 1) {
            mloc0 = fmaxf(mloc0, __shfl_xor_sync(0xffffffffu, mloc0, off));
            mloc1 = fmaxf(mloc1, __shfl_xor_sync(0xffffffffu, mloc1, off));
        }
        const float mnew0 = fmaxf(m_run0, mloc0);
        const float mnew1 = fmaxf(m_run1, mloc1);
        const float f0 = __expf(m_run0 - mnew0);
        const float f1 = __expf(m_run1 - mnew1);
        z_run0 *= f0; z_run1 *= f1;
        #pragma unroll
        for (int nt = 0; nt < 8; nt++) {
            Of[nt][0] *= f0; Of[nt][1] *= f0;
            Of[nt][2] *= f1; Of[nt][3] *= f1;
        }

        float zs0 = 0.f, zs1 = 0.f;
        float* Pp = sQP + (wid * 16 + g) * KP;
        #pragma unroll
        for (int nt = 0; nt < 8; nt++) {
            const float e0 = __expf(Sf[nt][0] - mnew0);
            const float e1 = __expf(Sf[nt][1] - mnew0);
            const float e2 = __expf(Sf[nt][2] - mnew1);
            const float e3 = __expf(Sf[nt][3] - mnew1);
            zs0 += e0 + e1; zs1 += e2 + e3;
            const int ki = kbase + nt * 8 + 2 * t;
            float2 p0, p1;
            p0.x = e0 * (md0[nt].x + (qi0 == ki     ? 1.f : 0.f));
            p0.y = e1 * (md0[nt].y + (qi0 == ki + 1 ? 1.f : 0.f));
            p1.x = e2 * (md1[nt].x + (qi1 == ki     ? 1.f : 0.f));
            p1.y = e3 * (md1[nt].y + (qi1 == ki + 1 ? 1.f : 0.f));
            *reinterpret_cast<float2*>(Pp + nt * 8 + 2 * t) = p0;
            *reinterpret_cast<float2*>(Pp + 8 * KP + nt * 8 + 2 * t) = p1;
        }
        #pragma unroll
        for (int off = 1; off <= 2; off <<= 1) {
            zs0 += __shfl_xor_sync(0xffffffffu, zs0, off);
            zs1 += __shfl_xor_sync(0xffffffffu, zs1, off);
        }
        z_run0 += zs0; z_run1 += zs1;
        m_run0 = mnew0; m_run1 = mnew1;
        __syncwarp();

        // ---- O += P V ----
        #pragma unroll
        for (int ks = 0; ks < 8; ks++) {
            uint32_t af[4];
            const float* pp = sQP + (wid * 16 + g) * KP + ks * 8 + t;
            af[0] = f2tf(pp[0]);
            af[1] = f2tf(pp[8 * KP]);
            af[2] = f2tf(pp[4]);
            af[3] = f2tf(pp[8 * KP + 4]);
            #pragma unroll
            for (int nt = 0; nt < 8; nt++) {
                const float* vp = Vs + (ks * 8 + t) * VP + nt * 8 + g;
                uint32_t bf[2] = { f2tf(vp[0]), f2tf(vp[4 * VP]) };
                mma8(Of[nt], af, bf);
            }
        }
        __syncthreads();
    }

    // ---- epilogue ----
    const float inv0 = 1.f / z_run0, inv1 = 1.f / z_run1;
    #pragma unroll
    for (int nt = 0; nt < 8; nt++) {
        const int d = h * DKH + nt * 8 + 2 * t;
        float2 v0, v1;
        v0.x = Of[nt][0] * inv0; v0.y = Of[nt][1] * inv0;
        v1.x = Of[nt][2] * inv1; v1.y = Of[nt][3] * inv1;
        *reinterpret_cast<float2*>(ctx + ((size_t)b * SEQ + qi0) * DIM + d) = v0;
        *reinterpret_cast<float2*>(ctx + ((size_t)b * SEQ + qi1) * DIM + d) = v1;
    }
}

// ======================================================================
// host orchestration
// ======================================================================
extern "C" void kernel_launch(void* const* d_in, const int* in_sizes, int n_in,
                              void* d_out, int out_size)
{
    const float* Q    = (const float*)d_in[0];
    const float* Kin  = (const float*)d_in[1];
    const float* Vin  = (const float*)d_in[2];
    const float* dist = (const float*)d_in[3];
    const float* Wq   = (const float*)d_in[4];
    const float* bq   = (const float*)d_in[5];
    const float* Wk   = (const float*)d_in[6];
    const float* bk   = (const float*)d_in[7];
    const float* Wv   = (const float*)d_in[8];
    const float* bv   = (const float*)d_in[9];
    const float* Wo   = (const float*)d_in[10];
    const float* bo   = (const float*)d_in[11];
    float* out = (float*)d_out;

    float *q_buf, *k_buf, *v_buf, *ctx_buf, *pp_buf;
    cudaGetSymbolAddress((void**)&q_buf,   g_q);
    cudaGetSymbolAddress((void**)&k_buf,   g_k);
    cudaGetSymbolAddress((void**)&v_buf,   g_v);
    cudaGetSymbolAddress((void**)&ctx_buf, g_ctx);
    cudaGetSymbolAddress((void**)&pp_buf,  g_pp);

    cudaFuncSetAttribute(gemm_mma_kernel,
                         cudaFuncAttributeMaxDynamicSharedMemorySize, GEMM_SMEM);
    cudaFuncSetAttribute(attn_mma_kernel,
                         cudaFuncAttributeMaxDynamicSharedMemorySize, ATTN_SMEM);

    dim3 ggrid(DIM / 128, MTOT / 128);  // (6, 64)
    dim3 agrid(SEQ / 128, NH, BSZ);     // (8, 12, 8)

    const float* curK = Kin;
    const float* curV = Vin;
    for (int i = 0; i < NL; i++) {
        const size_t wo = (size_t)i * DIM * DIM;
        const size_t bofs = (size_t)i * DIM;
        gemm_mma_kernel<<<ggrid, 256, GEMM_SMEM>>>(Q,    Wq + wo, bq + bofs, nullptr, q_buf);
        gemm_mma_kernel<<<ggrid, 256, GEMM_SMEM>>>(curK, Wk + wo, bk + bofs, nullptr, k_buf);
        gemm_mma_kernel<<<ggrid, 256, GEMM_SMEM>>>(curV, Wv + wo, bv + bofs, nullptr, v_buf);
        attn_mma_kernel<<<agrid, 256, ATTN_SMEM>>>(q_buf, k_buf, v_buf, dist, ctx_buf);
        float* dst = (i == NL - 1) ? out : pp_buf;
        gemm_mma_kernel<<<ggrid, 256, GEMM_SMEM>>>(ctx_buf, Wo + wo, bo + bofs,
                                                   (i == NL - 1) ? Vin : nullptr, dst);
        curK = dst;
        curV = dst;
    }
}

// round 4
// speedup vs baseline: 5.7022x; 1.7751x over previous
#include <cuda_runtime.h>
#include <cuda_bf16.h>
#include <cstdint>
#include <math.h>

#define BSZ 8
#define SEQ 1024
#define DIM 768
#define NH  12
#define DKH 64
#define NL  3
#define MTOT (BSZ*SEQ)   // 8192

// ---------------- scratch (no allocations allowed) ----------------
__device__ __nv_bfloat16 g_qin [MTOT*DIM];
__device__ __nv_bfloat16 g_kin [MTOT*DIM];
__device__ __nv_bfloat16 g_vin [MTOT*DIM];
__device__ __nv_bfloat16 g_qbf [MTOT*DIM];
__device__ __nv_bfloat16 g_kbf [MTOT*DIM];
__device__ __nv_bfloat16 g_vt  [MTOT*DIM];   // V transposed: [(b*12+h)*64+d][SEQ]
__device__ __nv_bfloat16 g_ctx [MTOT*DIM];
__device__ __nv_bfloat16 g_ppbf[MTOT*DIM];
__device__ __nv_bfloat16 g_wq  [NL*DIM*DIM];
__device__ __nv_bfloat16 g_wk  [NL*DIM*DIM];
__device__ __nv_bfloat16 g_wv  [NL*DIM*DIM];
__device__ __nv_bfloat16 g_wo  [NL*DIM*DIM];
__device__ float         g_deff[BSZ*SEQ*SEQ];  // dist + I

// ======================================================================
// helpers
// ======================================================================
__device__ __forceinline__ uint32_t smem_u32(const void* p) {
    uint32_t a;
    asm("{ .reg .u64 t; cvta.to.shared.u64 t, %1; cvt.u32.u64 %0, t; }"
        : "=r"(a) : "l"(p));
    return a;
}

// pack two fp32 -> bf16x2 (lo = first element in memory order)
__device__ __forceinline__ uint32_t pack_bf(float lo, float hi) {
    uint32_t r;
    asm("cvt.rn.bf16x2.f32 %0, %1, %2;" : "=r"(r) : "f"(hi), "f"(lo));
    return r;
}

// D += A*B, m16n8k16 bf16, fp32 accum
__device__ __forceinline__ void mma16(float* d, const uint32_t* a, const uint32_t* b) {
    asm volatile(
        "mma.sync.aligned.m16n8k16.row.col.f32.bf16.bf16.f32 "
        "{%0,%1,%2,%3}, {%4,%5,%6,%7}, {%8,%9}, {%0,%1,%2,%3};"
        : "+f"(d[0]), "+f"(d[1]), "+f"(d[2]), "+f"(d[3])
        : "r"(a[0]), "r"(a[1]), "r"(a[2]), "r"(a[3]), "r"(b[0]), "r"(b[1]));
}

#define CP_ASYNC16(s, g) \
    asm volatile("cp.async.cg.shared.global [%0], [%1], 16;" \
                 :: "r"(s), "l"(g) : "memory")
#define CP_COMMIT() asm volatile("cp.async.commit_group;" ::: "memory")
template<int N> __device__ __forceinline__ void cp_wait() {
    asm volatile("cp.async.wait_group %0;" :: "n"(N) : "memory");
}

// ======================================================================
// converters (run once per launch; ~30us total)
// ======================================================================
__global__ void f2bf_kernel(const float4* __restrict__ in, uint2* __restrict__ out, int n4) {
    int i = blockIdx.x * blockDim.x + threadIdx.x;
    if (i < n4) {
        float4 f = in[i];
        out[i] = make_uint2(pack_bf(f.x, f.y), pack_bf(f.z, f.w));
    }
}

__global__ void disteff_kernel(const float4* __restrict__ dist, float4* __restrict__ deff, int n4) {
    int i = blockIdx.x * blockDim.x + threadIdx.x;
    if (i < n4) {
        float4 f = dist[i];
        int base = i * 4;
        int j = base & (SEQ - 1);
        int r = (base >> 10) & (SEQ - 1);
        if (r == j)     f.x += 1.f;
        if (r == j + 1) f.y += 1.f;
        if (r == j + 2) f.z += 1.f;
        if (r == j + 3) f.w += 1.f;
        deff[i] = f;
    }
}

// ======================================================================
// bf16 GEMM: out = X[M,768] @ W[N,768]^T + bias
// CTA 128x128, K-chunk 32, 2-stage cp.async, 8 warps (4m x 2n).
// smem rows stride 40 bf16 (20 words) -> all fragment loads conflict-free.
// MODE 0: bf16 out (value*scale)   MODE 1: bf16 transposed (V layout)
// MODE 2: fp32 out + residual add
// ======================================================================
#define GPADW 20                    // words per smem row
#define GSLOTW (128*GPADW)          // words per A or B tile (2560)
#define GEMM_SMEM ((128 + 2*2*GSLOTW) * 4)   // 41472 B

template<int MODE>
__global__ __launch_bounds__(256, 2) void gemm_bf16_kernel(
    const __nv_bfloat16* __restrict__ X, const __nv_bfloat16* __restrict__ W,
    const float* __restrict__ bias, const float* __restrict__ add,
    void* __restrict__ outp, float scale)
{
    extern __shared__ __align__(128) float smf[];
    float* sBias = smf;
    uint32_t* sT  = (uint32_t*)(smf + 128);
    const uint32_t tAddr = smem_u32(sT);

    const int tid  = threadIdx.x;
    const int lane = tid & 31, wid = tid >> 5;
    const int g = lane >> 2, t = lane & 3;
    const int wm = wid & 3, wn = wid >> 2;
    const int m0 = blockIdx.y * 128, n0 = blockIdx.x * 128;

    if (tid < 128) sBias[tid] = bias[n0 + tid];

    float acc[2][8][4];
    #pragma unroll
    for (int mt = 0; mt < 2; mt++)
        #pragma unroll
        for (int nt = 0; nt < 8; nt++)
            #pragma unroll
            for (int i = 0; i < 4; i++) acc[mt][nt][i] = 0.f;

    auto load_chunk = [&](int c) {
        const uint32_t base = tAddr + (uint32_t)(c & 1) * (2 * GSLOTW * 4);
        const __nv_bfloat16* gA = X + (size_t)m0 * DIM + c * 32;
        const __nv_bfloat16* gB = W + (size_t)n0 * DIM + c * 32;
        #pragma unroll
        for (int i = 0; i < 2; i++) {
            int idx = tid + i * 256;          // 0..511
            int row = idx >> 2, f = idx & 3;  // 4x16B per row
            uint32_t d = base + (uint32_t)(row * GPADW + f * 4) * 4;
            const size_t go = (size_t)row * DIM + f * 8;
            CP_ASYNC16(d, gA + go);
            CP_ASYNC16(d + GSLOTW * 4, gB + go);
        }
        CP_COMMIT();
    };

    load_chunk(0);
    for (int c = 0; c < 24; c++) {
        if (c + 1 < 24) { load_chunk(c + 1); cp_wait<1>(); }
        else            cp_wait<0>();
        __syncthreads();

        const uint32_t* A = sT + (size_t)(c & 1) * 2 * GSLOTW;
        const uint32_t* B = A + GSLOTW;

        #pragma unroll
        for (int ks = 0; ks < 2; ks++) {
            uint32_t af[2][4];
            #pragma unroll
            for (int mt = 0; mt < 2; mt++) {
                const uint32_t* ap = A + (wm * 32 + mt * 16 + g) * GPADW + ks * 8 + t;
                af[mt][0] = ap[0];
                af[mt][1] = ap[8 * GPADW];
                af[mt][2] = ap[4];
                af[mt][3] = ap[8 * GPADW + 4];
            }
            #pragma unroll
            for (int nt = 0; nt < 8; nt++) {
                const uint32_t* bp = B + (wn * 64 + nt * 8 + g) * GPADW + ks * 8 + t;
                uint32_t bf[2] = { bp[0], bp[4] };
                mma16(acc[0][nt], af[0], bf);
                mma16(acc[1][nt], af[1], bf);
            }
        }
        __syncthreads();
    }

    // epilogue
    #pragma unroll
    for (int mt = 0; mt < 2; mt++) {
        const int m = m0 + wm * 32 + mt * 16 + g;
        #pragma unroll
        for (int nt = 0; nt < 8; nt++) {
            const int nl = wn * 64 + nt * 8 + 2 * t;
            float v0x = acc[mt][nt][0] + sBias[nl];
            float v0y = acc[mt][nt][1] + sBias[nl + 1];
            float v1x = acc[mt][nt][2] + sBias[nl];
            float v1y = acc[mt][nt][3] + sBias[nl + 1];
            if (MODE == 0) {
                v0x *= scale; v0y *= scale; v1x *= scale; v1y *= scale;
                __nv_bfloat16* ob = (__nv_bfloat16*)outp;
                *(uint32_t*)(ob + (size_t)m * DIM + n0 + nl)       = pack_bf(v0x, v0y);
                *(uint32_t*)(ob + (size_t)(m + 8) * DIM + n0 + nl) = pack_bf(v1x, v1y);
            } else if (MODE == 1) {
                // transposed V: vt[(b*768 + n)*1024 + s]
                __nv_bfloat16* ob = (__nv_bfloat16*)outp;
                const int n = n0 + nl;
                const size_t rb = (size_t)((m >> 10) * 768);
                const int s = m & (SEQ - 1);
                ob[(rb + n)     * SEQ + s]     = __float2bfloat16(v0x);
                ob[(rb + n + 1) * SEQ + s]     = __float2bfloat16(v0y);
                ob[(rb + n)     * SEQ + s + 8] = __float2bfloat16(v1x);
                ob[(rb + n + 1) * SEQ + s + 8] = __float2bfloat16(v1y);
            } else {
                float* of = (float*)outp;
                const size_t o0 = (size_t)m * DIM + n0 + nl;
                const size_t o1 = (size_t)(m + 8) * DIM + n0 + nl;
                float2 a0 = *reinterpret_cast<const float2*>(add + o0);
                float2 a1 = *reinterpret_cast<const float2*>(add + o1);
                *reinterpret_cast<float2*>(of + o0) = make_float2(v0x + a0.x, v0y + a0.y);
                *reinterpret_cast<float2*>(of + o1) = make_float2(v1x + a1.x, v1y + a1.y);
            }
        }
    }
}

// ======================================================================
// bf16 flash attention. CTA = (b, h, 128 q rows); warp w owns 16 q rows.
// K tile [64 seq][64 k] bf16, Vt tile [64 d][64 seq] bf16 (pre-transposed),
// double-buffered. Q/P share one [128][64] bf16 region. Stride 72 bf16
// (36 words) -> all patterns conflict-free. Scores pre-scaled (q *= 1/8
// folded into Q-GEMM); mask (dist+I) pre-built.
// ======================================================================
#define APW 36                       // words per row
#define KV_SLOTW (64*APW*2)          // K + Vt per stage (4608 words)
#define QP_OFFW  (2*KV_SLOTW)        // 9216 words
#define ATTN_SMEM ((2*KV_SLOTW + 128*APW) * 4)   // 55296 B

__global__ __launch_bounds__(256, 2) void attn_bf16_kernel(
    const __nv_bfloat16* __restrict__ q, const __nv_bfloat16* __restrict__ k,
    const __nv_bfloat16* __restrict__ vt, const float* __restrict__ deff,
    __nv_bfloat16* __restrict__ ctx)
{
    extern __shared__ __align__(128) uint32_t smw[];
    const uint32_t base = smem_u32(smw);
    uint32_t* sQP = smw + QP_OFFW;

    const int tid  = threadIdx.x;
    const int lane = tid & 31, wid = tid >> 5;
    const int g = lane >> 2, t = lane & 3;
    const int b = blockIdx.z, h = blockIdx.y;
    const int q0 = blockIdx.x * 128;

    const __nv_bfloat16* qb = q + (size_t)b * SEQ * DIM + h * DKH;
    const __nv_bfloat16* kb = k + (size_t)b * SEQ * DIM + h * DKH;
    const __nv_bfloat16* vb = vt + ((size_t)b * 768 + h * DKH) * SEQ;
    const float* db = deff + (size_t)b * SEQ * SEQ;

    // ---- load Q tile 128x64 bf16 via cp.async ----
    {
        const uint32_t qdst = base + QP_OFFW * 4;
        #pragma unroll
        for (int i = 0; i < 4; i++) {
            int idx = tid + i * 256;        // 0..1023
            int row = idx >> 3, f = idx & 7;
            CP_ASYNC16(qdst + (uint32_t)(row * APW + f * 4) * 4,
                       qb + (size_t)(q0 + row) * DIM + f * 8);
        }
        CP_COMMIT();
        cp_wait<0>();
        __syncthreads();
    }

    // ---- extract Q fragments once ----
    uint32_t qf[4][4];
    {
        const uint32_t* qp0 = sQP + (wid * 16 + g) * APW;
        const uint32_t* qp1 = qp0 + 8 * APW;
        #pragma unroll
        for (int ks = 0; ks < 4; ks++) {
            qf[ks][0] = qp0[ks * 8 + t];
            qf[ks][1] = qp1[ks * 8 + t];
            qf[ks][2] = qp0[ks * 8 + t + 4];
            qf[ks][3] = qp1[ks * 8 + t + 4];
        }
    }
    __syncthreads();    // sQP now reusable as P

    float Of[8][4];
    #pragma unroll
    for (int nt = 0; nt < 8; nt++)
        #pragma unroll
        for (int i = 0; i < 4; i++) Of[nt][i] = 0.f;
    float m_run0 = -1e30f, m_run1 = -1e30f, z_run0 = 0.f, z_run1 = 0.f;
    const int qi0 = q0 + wid * 16 + g;
    const int qi1 = qi0 + 8;

    auto load_kv = [&](int kt) {
        const uint32_t dst = base + (uint32_t)(kt & 1) * (KV_SLOTW * 4);
        const __nv_bfloat16* gk = kb + (size_t)kt * 64 * DIM;
        const __nv_bfloat16* gv = vb + kt * 64;
        #pragma unroll
        for (int i = 0; i < 4; i++) {
            int idx = tid + i * 256;        // 0..1023
            int row = idx >> 3, f = idx & 7;
            CP_ASYNC16(dst + (uint32_t)(row * APW + f * 4) * 4,
                       gk + (size_t)row * DIM + f * 8);
            CP_ASYNC16(dst + (uint32_t)(64 * APW + row * APW + f * 4) * 4,
                       gv + (size_t)row * SEQ + f * 8);
        }
        CP_COMMIT();
    };

    load_kv(0);
    for (int kt = 0; kt < 16; kt++) {
        if (kt + 1 < 16) { load_kv(kt + 1); cp_wait<1>(); }
        else             cp_wait<0>();
        __syncthreads();

        const uint32_t* Ks = smw + (size_t)(kt & 1) * KV_SLOTW;
        const uint32_t* Vs = Ks + 64 * APW;
        const int kbase = kt * 64;

        // ---- S = Q K^T (pre-scaled) ----
        float Sf[8][4];
        #pragma unroll
        for (int nt = 0; nt < 8; nt++)
            #pragma unroll
            for (int i = 0; i < 4; i++) Sf[nt][i] = 0.f;
        #pragma unroll
        for (int ks = 0; ks < 4; ks++) {
            #pragma unroll
            for (int nt = 0; nt < 8; nt++) {
                const uint32_t* kp = Ks + (nt * 8 + g) * APW + ks * 8 + t;
                uint32_t bf[2] = { kp[0], kp[4] };
                mma16(Sf[nt], qf[ks], bf);
            }
        }

        // ---- online softmax ----
        float mloc0 = -1e30f, mloc1 = -1e30f;
        #pragma unroll
        for (int nt = 0; nt < 8; nt++) {
            mloc0 = fmaxf(mloc0, fmaxf(Sf[nt][0], Sf[nt][1]));
            mloc1 = fmaxf(mloc1, fmaxf(Sf[nt][2], Sf[nt][3]));
        }
        #pragma unroll
        for (int off = 1; off <= 2; off <<= 1) {
            mloc0 = fmaxf(mloc0, __shfl_xor_sync(0xffffffffu, mloc0, off));
            mloc1 = fmaxf(mloc1, __shfl_xor_sync(0xffffffffu, mloc1, off));
        }
        const float mnew0 = fmaxf(m_run0, mloc0);
        const float mnew1 = fmaxf(m_run1, mloc1);
        const float f0 = __expf(m_run0 - mnew0);
        const float f1 = __expf(m_run1 - mnew1);
        z_run0 *= f0; z_run1 *= f1;
        #pragma unroll
        for (int nt = 0; nt < 8; nt++) {
            Of[nt][0] *= f0; Of[nt][1] *= f0;
            Of[nt][2] *= f1; Of[nt][3] *= f1;
        }

        float zs0 = 0.f, zs1 = 0.f;
        uint32_t* Pp0 = sQP + (wid * 16 + g) * APW;
        uint32_t* Pp1 = Pp0 + 8 * APW;
        #pragma unroll
        for (int h2 = 0; h2 < 2; h2++) {
            float2 md0[4], md1[4];
            #pragma unroll
            for (int j = 0; j < 4; j++) {
                const int nt = h2 * 4 + j;
                md0[j] = *reinterpret_cast<const float2*>(
                    db + (size_t)qi0 * SEQ + kbase + nt * 8 + 2 * t);
                md1[j] = *reinterpret_cast<const float2*>(
                    db + (size_t)qi1 * SEQ + kbase + nt * 8 + 2 * t);
            }
            #pragma unroll
            for (int j = 0; j < 4; j++) {
                const int nt = h2 * 4 + j;
                const float e0 = __expf(Sf[nt][0] - mnew0);
                const float e1 = __expf(Sf[nt][1] - mnew0);
                const float e2 = __expf(Sf[nt][2] - mnew1);
                const float e3 = __expf(Sf[nt][3] - mnew1);
                zs0 += e0 + e1; zs1 += e2 + e3;
                Pp0[nt * 4 + t] = pack_bf(e0 * md0[j].x, e1 * md0[j].y);
                Pp1[nt * 4 + t] = pack_bf(e2 * md1[j].x, e3 * md1[j].y);
            }
        }
        #pragma unroll
        for (int off = 1; off <= 2; off <<= 1) {
            zs0 += __shfl_xor_sync(0xffffffffu, zs0, off);
            zs1 += __shfl_xor_sync(0xffffffffu, zs1, off);
        }
        z_run0 += zs0; z_run1 += zs1;
        m_run0 = mnew0; m_run1 = mnew1;
        __syncwarp();

        // ---- O += P V  (P rows owned by this warp only) ----
        #pragma unroll
        for (int ks = 0; ks < 4; ks++) {
            uint32_t af[4];
            const uint32_t* pp0 = sQP + (wid * 16 + g) * APW + ks * 8 + t;
            af[0] = pp0[0];
            af[1] = pp0[8 * APW];
            af[2] = pp0[4];
            af[3] = pp0[8 * APW + 4];
            #pragma unroll
            for (int nt = 0; nt < 8; nt++) {
                const uint32_t* vp = Vs + (nt * 8 + g) * APW + ks * 8 + t;
                uint32_t bf[2] = { vp[0], vp[4] };
                mma16(Of[nt], af, bf);
            }
        }
        __syncthreads();
    }

    // ---- epilogue: normalize, pack bf16, store ctx [B,S,D] ----
    const float inv0 = 1.f / z_run0, inv1 = 1.f / z_run1;
    #pragma unroll
    for (int nt = 0; nt < 8; nt++) {
        const int d = h * DKH + nt * 8 + 2 * t;
        *(uint32_t*)(ctx + ((size_t)b * SEQ + qi0) * DIM + d) =
            pack_bf(Of[nt][0] * inv0, Of[nt][1] * inv0);
        *(uint32_t*)(ctx + ((size_t)b * SEQ + qi1) * DIM + d) =
            pack_bf(Of[nt][2] * inv1, Of[nt][3] * inv1);
    }
}

// ======================================================================
// host orchestration
// ======================================================================
extern "C" void kernel_launch(void* const* d_in, const int* in_sizes, int n_in,
                              void* d_out, int out_size)
{
    const float* Q    = (const float*)d_in[0];
    const float* Kin  = (const float*)d_in[1];
    const float* Vin  = (const float*)d_in[2];
    const float* dist = (const float*)d_in[3];
    const float* Wq   = (const float*)d_in[4];
    const float* bq   = (const float*)d_in[5];
    const float* Wk   = (const float*)d_in[6];
    const float* bk   = (const float*)d_in[7];
    const float* Wv   = (const float*)d_in[8];
    const float* bv   = (const float*)d_in[9];
    const float* Wo   = (const float*)d_in[10];
    const float* bo   = (const float*)d_in[11];
    float* out = (float*)d_out;

    __nv_bfloat16 *qin, *kin, *vin, *qbf, *kbf, *vtb, *ctxb, *ppb;
    __nv_bfloat16 *wqb, *wkb, *wvb, *wob;
    float* deff;
    cudaGetSymbolAddress((void**)&qin,  g_qin);
    cudaGetSymbolAddress((void**)&kin,  g_kin);
    cudaGetSymbolAddress((void**)&vin,  g_vin);
    cudaGetSymbolAddress((void**)&qbf,  g_qbf);
    cudaGetSymbolAddress((void**)&kbf,  g_kbf);
    cudaGetSymbolAddress((void**)&vtb,  g_vt);
    cudaGetSymbolAddress((void**)&ctxb, g_ctx);
    cudaGetSymbolAddress((void**)&ppb,  g_ppbf);
    cudaGetSymbolAddress((void**)&wqb,  g_wq);
    cudaGetSymbolAddress((void**)&wkb,  g_wk);
    cudaGetSymbolAddress((void**)&wvb,  g_wv);
    cudaGetSymbolAddress((void**)&wob,  g_wo);
    cudaGetSymbolAddress((void**)&deff, g_deff);

    cudaFuncSetAttribute(gemm_bf16_kernel<0>,
                         cudaFuncAttributeMaxDynamicSharedMemorySize, GEMM_SMEM);
    cudaFuncSetAttribute(gemm_bf16_kernel<1>,
                         cudaFuncAttributeMaxDynamicSharedMemorySize, GEMM_SMEM);
    cudaFuncSetAttribute(gemm_bf16_kernel<2>,
                         cudaFuncAttributeMaxDynamicSharedMemorySize, GEMM_SMEM);
    cudaFuncSetAttribute(attn_bf16_kernel,
                         cudaFuncAttributeMaxDynamicSharedMemorySize, ATTN_SMEM);

    // ---- one-time conversions ----
    {
        const int nAct4 = MTOT * DIM / 4;
        const int nW4   = NL * DIM * DIM / 4;
        const int nD4   = BSZ * SEQ * SEQ / 4;
        f2bf_kernel<<<(nAct4 + 255) / 256, 256>>>((const float4*)Q,   (uint2*)qin, nAct4);
        f2bf_kernel<<<(nAct4 + 255) / 256, 256>>>((const float4*)Kin, (uint2*)kin, nAct4);
        f2bf_kernel<<<(nAct4 + 255) / 256, 256>>>((const float4*)Vin, (uint2*)vin, nAct4);
        f2bf_kernel<<<(nW4 + 255) / 256, 256>>>((const float4*)Wq, (uint2*)wqb, nW4);
        f2bf_kernel<<<(nW4 + 255) / 256, 256>>>((const float4*)Wk, (uint2*)wkb, nW4);
        f2bf_kernel<<<(nW4 + 255) / 256, 256>>>((const float4*)Wv, (uint2*)wvb, nW4);
        f2bf_kernel<<<(nW4 + 255) / 256, 256>>>((const float4*)Wo, (uint2*)wob, nW4);
        disteff_kernel<<<(nD4 + 255) / 256, 256>>>((const float4*)dist, (float4*)deff, nD4);
    }

    dim3 ggrid(DIM / 128, MTOT / 128);  // (6, 64)
    dim3 agrid(SEQ / 128, NH, BSZ);     // (8, 12, 8)

    const __nv_bfloat16* curKV = nullptr;
    for (int i = 0; i < NL; i++) {
        const size_t wo = (size_t)i * DIM * DIM;
        const size_t bofs = (size_t)i * DIM;
        const __nv_bfloat16* xk = (i == 0) ? kin : ppb;
        const __nv_bfloat16* xv = (i == 0) ? vin : ppb;
        gemm_bf16_kernel<0><<<ggrid, 256, GEMM_SMEM>>>(qin, wqb + wo, bq + bofs, nullptr, qbf, 0.125f);
        gemm_bf16_kernel<0><<<ggrid, 256, GEMM_SMEM>>>(xk,  wkb + wo, bk + bofs, nullptr, kbf, 1.0f);
        gemm_bf16_kernel<1><<<ggrid, 256, GEMM_SMEM>>>(xv,  wvb + wo, bv + bofs, nullptr, vtb, 1.0f);
        attn_bf16_kernel<<<agrid, 256, ATTN_SMEM>>>(qbf, kbf, vtb, deff, ctxb);
        if (i < NL - 1)
            gemm_bf16_kernel<0><<<ggrid, 256, GEMM_SMEM>>>(ctxb, wob + wo, bo + bofs, nullptr, ppb, 1.0f);
        else
            gemm_bf16_kernel<2><<<ggrid, 256, GEMM_SMEM>>>(ctxb, wob + wo, bo + bofs, Vin, out, 1.0f);
        (void)curKV;
    }
}